// round 4
// baseline (speedup 1.0000x reference)
#include <cuda_runtime.h>
#include <cuda_bf16.h>
#include <math.h>

#define BB 16
#define SS 1024
#define DD 1024
#define EE 8
#define IM 2048
#define KCAP 256
#define UNCOND_LABEL 1000LL

#define BM 64
#define BN 64
#define BK 16

// ---------------- scratch (static device globals; no dynamic alloc) ----------
__device__ float g_cn[EE * DD];                     // normalized centers
__device__ float g_cos[BB * EE * SS];               // cosine sims (B,E,S)
__device__ float g_gate[BB * EE * KCAP];            // top-k gating weights
__device__ int   g_tok[BB * EE * KCAP];             // top-k token indices
__device__ float g_H1[(size_t)BB * SS * IM];        // 128MB: shared-/uncond-expert hidden
__device__ float g_HR[(size_t)BB * EE * KCAP * IM]; // 256MB: routed-expert hidden

// ---------------- center normalization ----------------
__global__ void k_norm_centers(const float* __restrict__ c) {
    int e = blockIdx.x;
    int tid = threadIdx.x;
    float ss = 0.f;
    for (int j = tid; j < DD; j += 256) {
        float v = c[e * DD + j];
        ss += v * v;
    }
    #pragma unroll
    for (int o = 16; o > 0; o >>= 1) ss += __shfl_down_sync(0xffffffffu, ss, o);
    __shared__ float red[8];
    if ((tid & 31) == 0) red[tid >> 5] = ss;
    __syncthreads();
    if (tid == 0) {
        float t = 0.f;
        for (int w = 0; w < 8; w++) t += red[w];
        red[0] = t;
    }
    __syncthreads();
    float inv = 1.f / fmaxf(sqrtf(red[0]), 1e-12f);
    for (int j = tid; j < DD; j += 256) g_cn[e * DD + j] = c[e * DD + j] * inv;
}

// ---------------- router: cos sims for one token vs all 8 centers -----------
__global__ void k_router(const float* __restrict__ hidden) {
    int t = blockIdx.x;             // 0..B*S-1
    int b = t >> 10;
    int s = t & 1023;
    int tid = threadIdx.x;          // 256
    const float* x = hidden + (size_t)t * DD;
    float acc[9];
    #pragma unroll
    for (int i = 0; i < 9; i++) acc[i] = 0.f;
    for (int j = tid; j < DD; j += 256) {
        float xv = x[j];
        acc[8] = fmaf(xv, xv, acc[8]);
        #pragma unroll
        for (int e = 0; e < EE; e++) acc[e] = fmaf(xv, g_cn[e * DD + j], acc[e]);
    }
    #pragma unroll
    for (int o = 16; o > 0; o >>= 1) {
        #pragma unroll
        for (int i = 0; i < 9; i++) acc[i] += __shfl_down_sync(0xffffffffu, acc[i], o);
    }
    __shared__ float sred[9 * 8];
    int lane = tid & 31, wid = tid >> 5;
    if (lane == 0) {
        #pragma unroll
        for (int i = 0; i < 9; i++) sred[i * 8 + wid] = acc[i];
    }
    __syncthreads();
    if (tid < EE) {
        float nrm = 0.f;
        for (int w = 0; w < 8; w++) nrm += sred[8 * 8 + w];
        nrm = fmaxf(sqrtf(nrm), 1e-12f);
        float d = 0.f;
        for (int w = 0; w < 8; w++) d += sred[tid * 8 + w];
        g_cos[((size_t)b * EE + tid) * SS + s] = d / nrm;
    }
}

// ---------------- softmax over S + top-256 (bitonic sort) per (b,e) ---------
__global__ void k_softmax_topk() {
    int r = blockIdx.x;            // 0..B*E-1
    int tid = threadIdx.x;         // 512
    __shared__ float v[SS];
    __shared__ int   ix[SS];
    __shared__ float red[16];
    const float* row = g_cos + (size_t)r * SS;

    float lmax = -1e30f;
    for (int i = tid; i < SS; i += 512) {
        float t = row[i];
        v[i] = t; ix[i] = i;
        lmax = fmaxf(lmax, t);
    }
    #pragma unroll
    for (int o = 16; o > 0; o >>= 1) lmax = fmaxf(lmax, __shfl_down_sync(0xffffffffu, lmax, o));
    if ((tid & 31) == 0) red[tid >> 5] = lmax;
    __syncthreads();
    if (tid == 0) {
        float m = red[0];
        for (int w = 1; w < 16; w++) m = fmaxf(m, red[w]);
        red[0] = m;
    }
    __syncthreads();
    float mx = red[0];
    __syncthreads();

    float lsum = 0.f;
    for (int i = tid; i < SS; i += 512) {
        float e_ = __expf(v[i] - mx);
        v[i] = e_;
        lsum += e_;
    }
    #pragma unroll
    for (int o = 16; o > 0; o >>= 1) lsum += __shfl_down_sync(0xffffffffu, lsum, o);
    if ((tid & 31) == 0) red[tid >> 5] = lsum;
    __syncthreads();
    if (tid == 0) {
        float s_ = 0.f;
        for (int w = 0; w < 16; w++) s_ += red[w];
        red[0] = s_;
    }
    __syncthreads();
    float inv = 1.f / red[0];
    for (int i = tid; i < SS; i += 512) v[i] *= inv;

    // bitonic sort, descending by value
    for (int k = 2; k <= SS; k <<= 1) {
        for (int j = k >> 1; j > 0; j >>= 1) {
            __syncthreads();
            for (int i = tid; i < SS; i += 512) {
                int p = i ^ j;
                if (p > i) {
                    bool dsc = ((i & k) == 0);
                    float vi = v[i], vp = v[p];
                    if (dsc ? (vi < vp) : (vi > vp)) {
                        v[i] = vp; v[p] = vi;
                        int tt = ix[i]; ix[i] = ix[p]; ix[p] = tt;
                    }
                }
            }
        }
    }
    __syncthreads();
    for (int i = tid; i < KCAP; i += 512) {
        g_gate[(size_t)r * KCAP + i] = v[i];
        g_tok[(size_t)r * KCAP + i]  = ix[i];
    }
}

// ---------------- dense fused gate+up GEMM: H = silu(A Wg) * (A Wu) ---------
// A: (B*S, D), Wg/Wu: (D, IM), H: (B*S, IM). mode: 0 = all rows, 1 = uncond rows.
__global__ void k_gateup_dense(const float* __restrict__ A,
                               const float* __restrict__ Bg,
                               const float* __restrict__ Bu,
                               const long long* __restrict__ labels,
                               int uncond) {
    const int K = DD, N = IM;
    int n0 = blockIdx.x * BN;
    int m0 = blockIdx.y * BM;
    if (uncond) {
        int b = m0 / SS;
        if (labels[b] != UNCOND_LABEL) return;
    }
    __shared__ float As[BK * BM];
    __shared__ float Bsg[BK * BN];
    __shared__ float Bsu[BK * BN];
    int tid = threadIdx.x;
    int tx = tid & 15, ty = tid >> 4;
    int arow = tid >> 2, acol = (tid & 3) << 2;
    int brow = tid >> 4, bcol = (tid & 15) << 2;
    float accg[16], accu[16];
    #pragma unroll
    for (int i = 0; i < 16; i++) { accg[i] = 0.f; accu[i] = 0.f; }

    const float* Aptr = A + (size_t)(m0 + arow) * K + acol;
    const float* Bgp = Bg + (size_t)brow * N + n0 + bcol;
    const float* Bup = Bu + (size_t)brow * N + n0 + bcol;

    for (int k0 = 0; k0 < K; k0 += BK) {
        float4 av = *(const float4*)(Aptr + k0);
        As[(acol + 0) * BM + arow] = av.x;
        As[(acol + 1) * BM + arow] = av.y;
        As[(acol + 2) * BM + arow] = av.z;
        As[(acol + 3) * BM + arow] = av.w;
        *(float4*)&Bsg[brow * BN + bcol] = *(const float4*)(Bgp + (size_t)k0 * N);
        *(float4*)&Bsu[brow * BN + bcol] = *(const float4*)(Bup + (size_t)k0 * N);
        __syncthreads();
        #pragma unroll
        for (int k = 0; k < BK; k++) {
            float4 a  = *(const float4*)&As[k * BM + ty * 4];
            float4 bg = *(const float4*)&Bsg[k * BN + tx * 4];
            float4 bu = *(const float4*)&Bsu[k * BN + tx * 4];
            float ar[4] = {a.x, a.y, a.z, a.w};
            float bgr[4] = {bg.x, bg.y, bg.z, bg.w};
            float bur[4] = {bu.x, bu.y, bu.z, bu.w};
            #pragma unroll
            for (int i = 0; i < 4; i++) {
                #pragma unroll
                for (int j = 0; j < 4; j++) {
                    accg[i * 4 + j] = fmaf(ar[i], bgr[j], accg[i * 4 + j]);
                    accu[i * 4 + j] = fmaf(ar[i], bur[j], accu[i * 4 + j]);
                }
            }
        }
        __syncthreads();
    }
    #pragma unroll
    for (int i = 0; i < 4; i++) {
        #pragma unroll
        for (int j = 0; j < 4; j++) {
            float gth = accg[i * 4 + j];
            float h = gth / (1.f + __expf(-gth)) * accu[i * 4 + j];
            g_H1[(size_t)(m0 + ty * 4 + i) * IM + n0 + tx * 4 + j] = h;
        }
    }
}

// ---------------- dense down GEMM: out (= or +=) H Wd -----------------------
__global__ void k_down_dense(const float* __restrict__ W,
                             float* __restrict__ outp,
                             const long long* __restrict__ labels,
                             int uncond) {
    const int K = IM, N = DD;
    int n0 = blockIdx.x * BN;
    int m0 = blockIdx.y * BM;
    if (uncond) {
        int b = m0 / SS;
        if (labels[b] != UNCOND_LABEL) return;
    }
    __shared__ float As[BK * BM];
    __shared__ float Bs[BK * BN];
    int tid = threadIdx.x;
    int tx = tid & 15, ty = tid >> 4;
    int arow = tid >> 2, acol = (tid & 3) << 2;
    int brow = tid >> 4, bcol = (tid & 15) << 2;
    float acc[16];
    #pragma unroll
    for (int i = 0; i < 16; i++) acc[i] = 0.f;

    const float* Aptr = g_H1 + (size_t)(m0 + arow) * K + acol;
    const float* Bp = W + (size_t)brow * N + n0 + bcol;

    for (int k0 = 0; k0 < K; k0 += BK) {
        float4 av = *(const float4*)(Aptr + k0);
        As[(acol + 0) * BM + arow] = av.x;
        As[(acol + 1) * BM + arow] = av.y;
        As[(acol + 2) * BM + arow] = av.z;
        As[(acol + 3) * BM + arow] = av.w;
        *(float4*)&Bs[brow * BN + bcol] = *(const float4*)(Bp + (size_t)k0 * N);
        __syncthreads();
        #pragma unroll
        for (int k = 0; k < BK; k++) {
            float4 a = *(const float4*)&As[k * BM + ty * 4];
            float4 b4 = *(const float4*)&Bs[k * BN + tx * 4];
            float ar[4] = {a.x, a.y, a.z, a.w};
            float br[4] = {b4.x, b4.y, b4.z, b4.w};
            #pragma unroll
            for (int i = 0; i < 4; i++)
                #pragma unroll
                for (int j = 0; j < 4; j++)
                    acc[i * 4 + j] = fmaf(ar[i], br[j], acc[i * 4 + j]);
        }
        __syncthreads();
    }
    #pragma unroll
    for (int i = 0; i < 4; i++) {
        #pragma unroll
        for (int j = 0; j < 4; j++) {
            size_t o = (size_t)(m0 + ty * 4 + i) * N + n0 + tx * 4 + j;
            if (uncond) outp[o] += acc[i * 4 + j];
            else        outp[o] = acc[i * 4 + j];
        }
    }
}

// ---------------- routed fused gate+up GEMM (gather A rows) -----------------
__global__ void k_gateup_routed(const float* __restrict__ hidden,
                                const float* __restrict__ Wg,
                                const float* __restrict__ Wu,
                                const long long* __restrict__ labels) {
    int g = blockIdx.z;           // 0..B*E-1
    int b = g >> 3, e = g & 7;
    if (labels[b] == UNCOND_LABEL) return;
    const int K = DD, N = IM;
    int n0 = blockIdx.x * BN;
    int m0 = blockIdx.y * BM;
    __shared__ float As[BK * BM];
    __shared__ float Bsg[BK * BN];
    __shared__ float Bsu[BK * BN];
    int tid = threadIdx.x;
    int tx = tid & 15, ty = tid >> 4;
    int arow = tid >> 2, acol = (tid & 3) << 2;
    int brow = tid >> 4, bcol = (tid & 15) << 2;
    float accg[16], accu[16];
    #pragma unroll
    for (int i = 0; i < 16; i++) { accg[i] = 0.f; accu[i] = 0.f; }

    int tok = g_tok[g * KCAP + m0 + arow];
    const float* Aptr = hidden + ((size_t)b * SS + tok) * K + acol;
    const float* Bgp = Wg + (size_t)e * DD * IM + (size_t)brow * N + n0 + bcol;
    const float* Bup = Wu + (size_t)e * DD * IM + (size_t)brow * N + n0 + bcol;

    for (int k0 = 0; k0 < K; k0 += BK) {
        float4 av = *(const float4*)(Aptr + k0);
        As[(acol + 0) * BM + arow] = av.x;
        As[(acol + 1) * BM + arow] = av.y;
        As[(acol + 2) * BM + arow] = av.z;
        As[(acol + 3) * BM + arow] = av.w;
        *(float4*)&Bsg[brow * BN + bcol] = *(const float4*)(Bgp + (size_t)k0 * N);
        *(float4*)&Bsu[brow * BN + bcol] = *(const float4*)(Bup + (size_t)k0 * N);
        __syncthreads();
        #pragma unroll
        for (int k = 0; k < BK; k++) {
            float4 a  = *(const float4*)&As[k * BM + ty * 4];
            float4 bg = *(const float4*)&Bsg[k * BN + tx * 4];
            float4 bu = *(const float4*)&Bsu[k * BN + tx * 4];
            float ar[4] = {a.x, a.y, a.z, a.w};
            float bgr[4] = {bg.x, bg.y, bg.z, bg.w};
            float bur[4] = {bu.x, bu.y, bu.z, bu.w};
            #pragma unroll
            for (int i = 0; i < 4; i++) {
                #pragma unroll
                for (int j = 0; j < 4; j++) {
                    accg[i * 4 + j] = fmaf(ar[i], bgr[j], accg[i * 4 + j]);
                    accu[i * 4 + j] = fmaf(ar[i], bur[j], accu[i * 4 + j]);
                }
            }
        }
        __syncthreads();
    }
    float* Hg = g_HR + (size_t)g * KCAP * IM;
    #pragma unroll
    for (int i = 0; i < 4; i++) {
        #pragma unroll
        for (int j = 0; j < 4; j++) {
            float gth = accg[i * 4 + j];
            float h = gth / (1.f + __expf(-gth)) * accu[i * 4 + j];
            Hg[(size_t)(m0 + ty * 4 + i) * IM + n0 + tx * 4 + j] = h;
        }
    }
}

// ---------------- routed down GEMM + gated scatter-add ----------------------
__global__ void k_down_routed(const float* __restrict__ Wd,
                              float* __restrict__ outp,
                              const long long* __restrict__ labels) {
    int g = blockIdx.z;
    int b = g >> 3, e = g & 7;
    if (labels[b] == UNCOND_LABEL) return;
    const int K = IM, N = DD;
    int n0 = blockIdx.x * BN;
    int m0 = blockIdx.y * BM;
    __shared__ float As[BK * BM];
    __shared__ float Bs[BK * BN];
    int tid = threadIdx.x;
    int tx = tid & 15, ty = tid >> 4;
    int arow = tid >> 2, acol = (tid & 3) << 2;
    int brow = tid >> 4, bcol = (tid & 15) << 2;
    float acc[16];
    #pragma unroll
    for (int i = 0; i < 16; i++) acc[i] = 0.f;

    const float* Aptr = g_HR + (size_t)g * KCAP * IM + (size_t)(m0 + arow) * K + acol;
    const float* Bp = Wd + (size_t)e * IM * DD + (size_t)brow * N + n0 + bcol;

    for (int k0 = 0; k0 < K; k0 += BK) {
        float4 av = *(const float4*)(Aptr + k0);
        As[(acol + 0) * BM + arow] = av.x;
        As[(acol + 1) * BM + arow] = av.y;
        As[(acol + 2) * BM + arow] = av.z;
        As[(acol + 3) * BM + arow] = av.w;
        *(float4*)&Bs[brow * BN + bcol] = *(const float4*)(Bp + (size_t)k0 * N);
        __syncthreads();
        #pragma unroll
        for (int k = 0; k < BK; k++) {
            float4 a = *(const float4*)&As[k * BM + ty * 4];
            float4 b4 = *(const float4*)&Bs[k * BN + tx * 4];
            float ar[4] = {a.x, a.y, a.z, a.w};
            float br[4] = {b4.x, b4.y, b4.z, b4.w};
            #pragma unroll
            for (int i = 0; i < 4; i++)
                #pragma unroll
                for (int j = 0; j < 4; j++)
                    acc[i * 4 + j] = fmaf(ar[i], br[j], acc[i * 4 + j]);
        }
        __syncthreads();
    }
    #pragma unroll
    for (int i = 0; i < 4; i++) {
        int row = m0 + ty * 4 + i;
        int tok = g_tok[g * KCAP + row];
        float w = g_gate[g * KCAP + row];
        float* orow = outp + ((size_t)b * SS + tok) * DD + n0 + tx * 4;
        #pragma unroll
        for (int j = 0; j < 4; j++) atomicAdd(&orow[j], w * acc[i * 4 + j]);
    }
}

// ---------------- launch ----------------------------------------------------
extern "C" void kernel_launch(void* const* d_in, const int* in_sizes, int n_in,
                              void* d_out, int out_size) {
    const float* hidden = (const float*)d_in[0];
    const long long* labels = (const long long*)d_in[1];
    const float* centers = (const float*)d_in[2];
    const float* Wg = (const float*)d_in[3];
    const float* Wu = (const float*)d_in[4];
    const float* Wd = (const float*)d_in[5];
    const float* uWg = (const float*)d_in[6];
    const float* uWu = (const float*)d_in[7];
    const float* uWd = (const float*)d_in[8];
    const float* sWg = (const float*)d_in[9];
    const float* sWu = (const float*)d_in[10];
    const float* sWd = (const float*)d_in[11];
    float* outp = (float*)d_out;

    // router
    k_norm_centers<<<EE, 256>>>(centers);
    k_router<<<BB * SS, 256>>>(hidden);
    k_softmax_topk<<<BB * EE, 512>>>();

    // shared expert (writes out fully)
    k_gateup_dense<<<dim3(IM / BN, (BB * SS) / BM), 256>>>(hidden, sWg, sWu, labels, 0);
    k_down_dense<<<dim3(DD / BN, (BB * SS) / BM), 256>>>(sWd, outp, labels, 0);

    // uncond expert (only batches with label == 1000), reuses g_H1
    k_gateup_dense<<<dim3(IM / BN, (BB * SS) / BM), 256>>>(hidden, uWg, uWu, labels, 1);
    k_down_dense<<<dim3(DD / BN, (BB * SS) / BM), 256>>>(uWd, outp, labels, 1);

    // routed experts (only batches with label != 1000)
    k_gateup_routed<<<dim3(IM / BN, KCAP / BM, BB * EE), 256>>>(hidden, Wg, Wu, labels);
    k_down_routed<<<dim3(DD / BN, KCAP / BM, BB * EE), 256>>>(Wd, outp, labels);
}

// round 11
// speedup vs baseline: 1.2386x; 1.2386x over previous
#include <cuda_runtime.h>
#include <cuda_bf16.h>
#include <mma.h>
#include <math.h>
#include <stdint.h>

using namespace nvcuda;

#define BB 16
#define SS 1024
#define DD 1024
#define EE 8
#define IM 2048
#define KCAP 256
#define UNCOND_LABEL 1000LL
#define NTOK (BB*SS)
#define NROUT (BB*EE*KCAP)

typedef __nv_bfloat16 bf16;

// gateup stage: sAh@0(10240) sAl@10240 | B@20480: per-mat 9216 (hi4608+lo4608) x2
#define GU_SMEM (1024 + 38912)
// down stage:   sAh@0(10240) sAl@10240 | Bh@20480(8704) Bl@29184(8704)
#define DN_SMEM (1024 + 37888)

// ---------------- scratch (269MB total — below proven-working 384MB) --------
__device__ float g_cn[EE*DD];
__device__ float g_cos[BB*EE*SS];
__device__ float g_gate[NROUT];
__device__ int   g_tok[NROUT];
__device__ float g_H[(size_t)NROUT * IM];   // 268MB fp32; dense uses rows 0..16383

// ---------------- split helper ----------------
__device__ __forceinline__ void split4(float4 v, uint2& hp, uint2& lp) {
    float vv[4] = {v.x, v.y, v.z, v.w};
    __align__(8) bf16 h[4];
    __align__(8) bf16 l[4];
    #pragma unroll
    for (int j = 0; j < 4; j++) {
        h[j] = __float2bfloat16_rn(vv[j]);
        l[j] = __float2bfloat16_rn(vv[j] - __bfloat162float(h[j]));
    }
    hp = *(uint2*)h; lp = *(uint2*)l;
}

// ---------------- router (proven correct) ----------------
__global__ void k_norm_centers(const float* __restrict__ c) {
    int e = blockIdx.x, tid = threadIdx.x;
    float ss = 0.f;
    for (int j = tid; j < DD; j += 256) { float v = c[e*DD+j]; ss += v*v; }
    #pragma unroll
    for (int o = 16; o > 0; o >>= 1) ss += __shfl_down_sync(0xffffffffu, ss, o);
    __shared__ float red[8];
    if ((tid & 31) == 0) red[tid>>5] = ss;
    __syncthreads();
    if (tid == 0) { float t = 0.f; for (int w = 0; w < 8; w++) t += red[w]; red[0] = t; }
    __syncthreads();
    float inv = 1.f / fmaxf(sqrtf(red[0]), 1e-12f);
    for (int j = tid; j < DD; j += 256) g_cn[e*DD+j] = c[e*DD+j] * inv;
}

__global__ void k_router(const float* __restrict__ hidden) {
    int t = blockIdx.x, b = t >> 10, s = t & 1023, tid = threadIdx.x;
    const float* x = hidden + (size_t)t * DD;
    float acc[9];
    #pragma unroll
    for (int i = 0; i < 9; i++) acc[i] = 0.f;
    for (int j = tid; j < DD; j += 256) {
        float xv = x[j];
        acc[8] = fmaf(xv, xv, acc[8]);
        #pragma unroll
        for (int e = 0; e < EE; e++) acc[e] = fmaf(xv, g_cn[e*DD+j], acc[e]);
    }
    #pragma unroll
    for (int o = 16; o > 0; o >>= 1) {
        #pragma unroll
        for (int i = 0; i < 9; i++) acc[i] += __shfl_down_sync(0xffffffffu, acc[i], o);
    }
    __shared__ float sr[72];
    int lane = tid & 31, wd = tid >> 5;
    if (lane == 0) {
        #pragma unroll
        for (int i = 0; i < 9; i++) sr[i*8+wd] = acc[i];
    }
    __syncthreads();
    if (tid < EE) {
        float nrm = 0.f;
        for (int w = 0; w < 8; w++) nrm += sr[64+w];
        nrm = fmaxf(sqrtf(nrm), 1e-12f);
        float d = 0.f;
        for (int w = 0; w < 8; w++) d += sr[tid*8+w];
        g_cos[((size_t)b*EE+tid)*SS + s] = d / nrm;
    }
}

__global__ void k_softmax_topk() {
    int r = blockIdx.x, tid = threadIdx.x;
    __shared__ float v[SS]; __shared__ int ix[SS]; __shared__ float red[16];
    const float* row = g_cos + (size_t)r * SS;
    float lmax = -1e30f;
    for (int i = tid; i < SS; i += 512) { float t = row[i]; v[i] = t; ix[i] = i; lmax = fmaxf(lmax, t); }
    #pragma unroll
    for (int o = 16; o > 0; o >>= 1) lmax = fmaxf(lmax, __shfl_down_sync(0xffffffffu, lmax, o));
    if ((tid & 31) == 0) red[tid>>5] = lmax;
    __syncthreads();
    if (tid == 0) { float m = red[0]; for (int w = 1; w < 16; w++) m = fmaxf(m, red[w]); red[0] = m; }
    __syncthreads();
    float mx = red[0];
    __syncthreads();
    float lsum = 0.f;
    for (int i = tid; i < SS; i += 512) { float e_ = __expf(v[i] - mx); v[i] = e_; lsum += e_; }
    #pragma unroll
    for (int o = 16; o > 0; o >>= 1) lsum += __shfl_down_sync(0xffffffffu, lsum, o);
    if ((tid & 31) == 0) red[tid>>5] = lsum;
    __syncthreads();
    if (tid == 0) { float s_ = 0.f; for (int w = 0; w < 16; w++) s_ += red[w]; red[0] = s_; }
    __syncthreads();
    float inv = 1.f / red[0];
    for (int i = tid; i < SS; i += 512) v[i] *= inv;
    for (int k = 2; k <= SS; k <<= 1)
        for (int j = k >> 1; j > 0; j >>= 1) {
            __syncthreads();
            for (int i = tid; i < SS; i += 512) {
                int p = i ^ j;
                if (p > i) {
                    bool dsc = ((i & k) == 0);
                    float vi = v[i], vp = v[p];
                    if (dsc ? (vi < vp) : (vi > vp)) {
                        v[i] = vp; v[p] = vi;
                        int tt = ix[i]; ix[i] = ix[p]; ix[p] = tt;
                    }
                }
            }
        }
    __syncthreads();
    for (int i = tid; i < KCAP; i += 512) {
        g_gate[(size_t)r*KCAP+i] = v[i];
        g_tok[(size_t)r*KCAP+i]  = ix[i];
    }
}

// ---------------- fused gate+up wmma GEMM -----------------------------------
// H[r][n] = silu(A·Wg)[r][n] * (A·Wu)[r][n].  A fp32 [*][DD] (opt gathered),
// Wg/Wu fp32 [DD][IM] (opt per-expert offset).  On-the-fly bf16 hi/lo split,
// 3-product accumulate.  CTA tile 128m x 64n, 8 warps (2m x 4n).
// pmode: 0 none; 1 uncond (b=y>>3); 2 routed (b=y>>4)
__global__ void __launch_bounds__(256) k_gateup(
    const float* __restrict__ A, const float* __restrict__ Wg,
    const float* __restrict__ Wu, float* __restrict__ Hout,
    const long long* __restrict__ labels, int gather, int wexp, int pmode)
{
    extern __shared__ __align__(16) char smem[];
    const int tid = threadIdx.x;
    const int y = blockIdx.y;
    const int n0 = blockIdx.x * 64;
    if (pmode == 1) { if (labels[y >> 3] != UNCOND_LABEL) return; }
    if (pmode == 2) { if (labels[y >> 4] == UNCOND_LABEL) return; }
    if (wexp) {
        size_t wo = (size_t)((y >> 1) & 7) * DD * IM;
        Wg += wo; Wu += wo;
    }
    int* arow = (int*)smem;
    if (tid < 128) {
        int r;
        if (gather) { int rowg = y * 128 + tid; r = (rowg >> 11) * SS + g_tok[rowg]; }
        else        r = y * 128 + tid;
        arow[tid] = r;
    }
    __syncthreads();

    const int lane = tid & 31, w = tid >> 5;
    const int wm = w & 1, wn = w >> 1;

    wmma::fragment<wmma::accumulator, 16, 16, 16, float> accg[4], accu[4];
    #pragma unroll
    for (int mi = 0; mi < 4; mi++) { wmma::fill_fragment(accg[mi], 0.f); wmma::fill_fragment(accu[mi], 0.f); }

    const bf16* sA  = (const bf16*)(smem + 1024);            // hi; lo at +5120 elems
    const bf16* sBg = (const bf16*)(smem + 1024 + 20480);    // hi; lo at +2304 elems
    const bf16* sBu = (const bf16*)(smem + 1024 + 20480 + 9216);

    for (int k0 = 0; k0 < DD; k0 += 32) {
        __syncthreads();
        // stage A: 128 rows x 32k, split
        #pragma unroll
        for (int i = 0; i < 4; i++) {
            int idx = i * 256 + tid;
            int row = idx >> 3, f4 = idx & 7;
            float4 v = *(const float4*)(A + (size_t)arow[row] * DD + k0 + f4 * 4);
            uint2 hp, lp; split4(v, hp, lp);
            *(uint2*)(smem + 1024 + row * 80 + f4 * 8)         = hp;
            *(uint2*)(smem + 1024 + 10240 + row * 80 + f4 * 8) = lp;
        }
        // stage B: Wg,Wu rows [k0..k0+32) x cols [n0..n0+64), layout [k][n], split
        #pragma unroll
        for (int i = 0; i < 4; i++) {
            int idx = i * 256 + tid;
            int mat = idx >> 9, rem = idx & 511;
            int k = rem >> 4, f4 = rem & 15;
            const float* src = (mat ? Wu : Wg) + (size_t)(k0 + k) * IM + n0 + f4 * 4;
            float4 v = *(const float4*)src;
            uint2 hp, lp; split4(v, hp, lp);
            char* bb = smem + 1024 + 20480 + mat * 9216 + k * 144 + f4 * 8;
            *(uint2*)bb          = hp;
            *(uint2*)(bb + 4608) = lp;
        }
        __syncthreads();
        #pragma unroll
        for (int kk = 0; kk < 32; kk += 16) {
            wmma::fragment<wmma::matrix_b, 16, 16, 16, bf16, wmma::row_major> fgh, fgl, fuh, ful;
            wmma::load_matrix_sync(fgh, sBg + kk * 72 + wn * 16, 72);
            wmma::load_matrix_sync(fgl, sBg + 2304 + kk * 72 + wn * 16, 72);
            wmma::load_matrix_sync(fuh, sBu + kk * 72 + wn * 16, 72);
            wmma::load_matrix_sync(ful, sBu + 2304 + kk * 72 + wn * 16, 72);
            #pragma unroll
            for (int mi = 0; mi < 4; mi++) {
                wmma::fragment<wmma::matrix_a, 16, 16, 16, bf16, wmma::row_major> fah, fal;
                const bf16* ap = sA + (wm * 64 + mi * 16) * 40 + kk;
                wmma::load_matrix_sync(fah, ap, 40);
                wmma::load_matrix_sync(fal, ap + 5120, 40);
                wmma::mma_sync(accg[mi], fah, fgh, accg[mi]);
                wmma::mma_sync(accg[mi], fah, fgl, accg[mi]);
                wmma::mma_sync(accg[mi], fal, fgh, accg[mi]);
                wmma::mma_sync(accu[mi], fah, fuh, accu[mi]);
                wmma::mma_sync(accu[mi], fah, ful, accu[mi]);
                wmma::mma_sync(accu[mi], fal, fuh, accu[mi]);
            }
        }
    }
    __syncthreads();   // stage SMEM now reusable as epilogue scratch

    float* sg = (float*)(smem + 1024 + w * 2560);   // 16x20 f32
    float* su = sg + 320;
    #pragma unroll
    for (int mi = 0; mi < 4; mi++) {
        wmma::store_matrix_sync(sg, accg[mi], 20, wmma::mem_row_major);
        wmma::store_matrix_sync(su, accu[mi], 20, wmma::mem_row_major);
        __syncwarp();
        int rb = y * 128 + wm * 64 + mi * 16;
        int cb = n0 + wn * 16;
        #pragma unroll
        for (int t = 0; t < 8; t++) {
            int idx = lane * 8 + t;
            int r16 = idx >> 4, c16 = idx & 15;
            float g = sg[r16 * 20 + c16];
            float u = su[r16 * 20 + c16];
            float h = g / (1.f + __expf(-g)) * u;
            g_H[(size_t)(rb + r16) * IM + cb + c16] = h;
        }
        __syncwarp();
    }
    (void)Hout;
}

// ---------------- down wmma GEMM: C = H · W  --------------------------------
// H fp32 [*][IM], W fp32 [IM][DD].  CTA tile 128m x 128n, 8 warps (2m x 4n).
// emode: 0 out=C; 1 out+=C; 2 atomicAdd(scatter, gate*C)
__global__ void __launch_bounds__(256) k_down(
    const float* __restrict__ W, float* __restrict__ outp,
    const long long* __restrict__ labels, int wexp, int pmode, int emode)
{
    extern __shared__ __align__(16) char smem[];
    const int tid = threadIdx.x;
    const int y = blockIdx.y;
    const int n0 = blockIdx.x * 128;
    if (pmode == 1) { if (labels[y >> 3] != UNCOND_LABEL) return; }
    if (pmode == 2) { if (labels[y >> 4] == UNCOND_LABEL) return; }
    if (wexp) W += (size_t)((y >> 1) & 7) * IM * DD;

    const int lane = tid & 31, w = tid >> 5;
    const int wm = w & 1, wn = w >> 1;

    wmma::fragment<wmma::accumulator, 16, 16, 16, float> acc[4][2];
    #pragma unroll
    for (int mi = 0; mi < 4; mi++)
        #pragma unroll
        for (int nj = 0; nj < 2; nj++) wmma::fill_fragment(acc[mi][nj], 0.f);

    const bf16* sA = (const bf16*)(smem + 1024);           // hi; lo +5120 elems
    const bf16* sB = (const bf16*)(smem + 1024 + 20480);   // hi; lo +4352 elems

    for (int k0 = 0; k0 < IM; k0 += 32) {
        __syncthreads();
        #pragma unroll
        for (int i = 0; i < 4; i++) {           // A: H rows
            int idx = i * 256 + tid;
            int row = idx >> 3, f4 = idx & 7;
            float4 v = *(const float4*)(g_H + (size_t)(y * 128 + row) * IM + k0 + f4 * 4);
            uint2 hp, lp; split4(v, hp, lp);
            *(uint2*)(smem + 1024 + row * 80 + f4 * 8)         = hp;
            *(uint2*)(smem + 1024 + 10240 + row * 80 + f4 * 8) = lp;
        }
        #pragma unroll
        for (int i = 0; i < 4; i++) {           // B: W [k][n] tile 32x128
            int idx = i * 256 + tid;
            int k = idx >> 5, f4 = idx & 31;
            float4 v = *(const float4*)(W + (size_t)(k0 + k) * DD + n0 + f4 * 4);
            uint2 hp, lp; split4(v, hp, lp);
            char* bb = smem + 1024 + 20480 + k * 272 + f4 * 8;
            *(uint2*)bb          = hp;
            *(uint2*)(bb + 8704) = lp;
        }
        __syncthreads();
        #pragma unroll
        for (int kk = 0; kk < 32; kk += 16) {
            wmma::fragment<wmma::matrix_b, 16, 16, 16, bf16, wmma::row_major> fbh[2], fbl[2];
            #pragma unroll
            for (int nj = 0; nj < 2; nj++) {
                const bf16* bp = sB + kk * 136 + wn * 32 + nj * 16;
                wmma::load_matrix_sync(fbh[nj], bp, 136);
                wmma::load_matrix_sync(fbl[nj], bp + 4352, 136);
            }
            #pragma unroll
            for (int mi = 0; mi < 4; mi++) {
                wmma::fragment<wmma::matrix_a, 16, 16, 16, bf16, wmma::row_major> fah, fal;
                const bf16* ap = sA + (wm * 64 + mi * 16) * 40 + kk;
                wmma::load_matrix_sync(fah, ap, 40);
                wmma::load_matrix_sync(fal, ap + 5120, 40);
                #pragma unroll
                for (int nj = 0; nj < 2; nj++) {
                    wmma::mma_sync(acc[mi][nj], fah, fbh[nj], acc[mi][nj]);
                    wmma::mma_sync(acc[mi][nj], fah, fbl[nj], acc[mi][nj]);
                    wmma::mma_sync(acc[mi][nj], fal, fbh[nj], acc[mi][nj]);
                }
            }
        }
    }
    __syncthreads();

    float* scr = (float*)(smem + 1024 + w * 1280);
    #pragma unroll
    for (int mi = 0; mi < 4; mi++) {
        #pragma unroll
        for (int nj = 0; nj < 2; nj++) {
            wmma::store_matrix_sync(scr, acc[mi][nj], 20, wmma::mem_row_major);
            __syncwarp();
            int rb = y * 128 + wm * 64 + mi * 16;
            int cb = n0 + wn * 32 + nj * 16;
            #pragma unroll
            for (int t = 0; t < 8; t++) {
                int idx = lane * 8 + t;
                int r16 = idx >> 4, c16 = idx & 15;
                float v = scr[r16 * 20 + c16];
                int r = rb + r16, c = cb + c16;
                if (emode == 0)      outp[(size_t)r * DD + c] = v;
                else if (emode == 1) outp[(size_t)r * DD + c] += v;
                else {
                    int tok = g_tok[r];
                    float wgt = g_gate[r];
                    int b = r >> 11;
                    atomicAdd(&outp[((size_t)b * SS + tok) * DD + c], wgt * v);
                }
            }
            __syncwarp();
        }
    }
}

// ---------------- launch ----------------------------------------------------
extern "C" void kernel_launch(void* const* d_in, const int* in_sizes, int n_in,
                              void* d_out, int out_size) {
    const float* hidden = (const float*)d_in[0];
    const long long* labels = (const long long*)d_in[1];
    const float* centers = (const float*)d_in[2];
    const float* Wg = (const float*)d_in[3];
    const float* Wu = (const float*)d_in[4];
    const float* Wd = (const float*)d_in[5];
    const float* uWg = (const float*)d_in[6];
    const float* uWu = (const float*)d_in[7];
    const float* uWd = (const float*)d_in[8];
    const float* sWg = (const float*)d_in[9];
    const float* sWu = (const float*)d_in[10];
    const float* sWd = (const float*)d_in[11];
    float* outp = (float*)d_out;

    // router
    k_norm_centers<<<EE, 256>>>(centers);
    k_router<<<BB * SS, 256>>>(hidden);
    k_softmax_topk<<<BB * EE, 512>>>();

    // shared expert: fused gateup -> H (fp32), down -> out (full store)
    k_gateup<<<dim3(IM/64, NTOK/128), 256, GU_SMEM>>>(hidden, sWg, sWu, g_H, labels, 0, 0, 0);
    k_down  <<<dim3(DD/128, NTOK/128), 256, DN_SMEM>>>(sWd, outp, labels, 0, 0, 0);

    // uncond expert (label==1000 batches), reuses g_H
    k_gateup<<<dim3(IM/64, NTOK/128), 256, GU_SMEM>>>(hidden, uWg, uWu, g_H, labels, 0, 0, 1);
    k_down  <<<dim3(DD/128, NTOK/128), 256, DN_SMEM>>>(uWd, outp, labels, 0, 1, 1);

    // routed experts (gathered A, per-expert weights, gated atomic scatter)
    k_gateup<<<dim3(IM/64, NROUT/128), 256, GU_SMEM>>>(hidden, Wg, Wu, g_H, labels, 1, 1, 2);
    k_down  <<<dim3(DD/128, NROUT/128), 256, DN_SMEM>>>(Wd, outp, labels, 1, 2, 2);
}